// round 14
// baseline (speedup 1.0000x reference)
#include <cuda_runtime.h>
#include <cuda_bf16.h>
#include <cuda_fp8.h>
#include <math.h>

// ----- scratch (no allocations allowed) -----
#define NODE_CAP 131072
__device__ float g_node_sum[NODE_CAP];
// fp8(e4m3) copies of Q,K: one row = 64 fp8 = 64 B = 4 uint4
__device__ uint4 gQ8[NODE_CAP * 4];
__device__ uint4 gK8[NODE_CAP * 4];

// --- PDL primitives (sm_90+) ---
__device__ __forceinline__ void pdl_wait() {
    asm volatile("griddepcontrol.wait;" ::: "memory");
}
__device__ __forceinline__ void pdl_launch_dependents() {
    asm volatile("griddepcontrol.launch_dependents;" ::: "memory");
}

// Streaming (evict-first) loads for read-once data.
__device__ __forceinline__ float4 ldcs_f4(const float4* p) { return __ldcs(p); }
__device__ __forceinline__ int    ldcs_i (const int* p)    { return __ldcs(p); }

__device__ __forceinline__ unsigned pack4_fp8(float4 a) {
    unsigned short lo = __nv_cvt_float2_to_fp8x2(make_float2(a.x, a.y), __NV_SATFINITE, __NV_E4M3);
    unsigned short hi = __nv_cvt_float2_to_fp8x2(make_float2(a.z, a.w), __NV_SATFINITE, __NV_E4M3);
    return (unsigned)lo | ((unsigned)hi << 16);
}

// fp32 -> fp8 conversion, transposed coalesced mapping (thread i -> one float4),
// 4x unrolled (indices i, i+s, i+2s, i+3s) -> 8 independent LDG.128 in flight.
// Streaming loads are single-line -> no L1tex queue cliff (unlike gathers).
// Fused zeroing of g_node_sum and out.
__global__ void convert_zero_kernel(const float4* __restrict__ Q,
                                    const float4* __restrict__ K,
                                    float* __restrict__ out,
                                    int total16 /* num_nodes*16 */,
                                    int num_nodes, int num_graphs) {
    unsigned* dQ = (unsigned*)gQ8;
    unsigned* dK = (unsigned*)gK8;
    int stride = gridDim.x * blockDim.x;
    int i = blockIdx.x * blockDim.x + threadIdx.x;
    if (i < num_nodes) g_node_sum[i] = 0.0f;
    if (i < num_graphs) out[i] = 0.0f;

    for (; i + 3 * stride < total16; i += 4 * stride) {
        int i1 = i + stride, i2 = i + 2 * stride, i3 = i + 3 * stride;
        float4 q0 = ldcs_f4(Q + i);
        float4 k0 = ldcs_f4(K + i);
        float4 q1 = ldcs_f4(Q + i1);
        float4 k1 = ldcs_f4(K + i1);
        float4 q2 = ldcs_f4(Q + i2);
        float4 k2 = ldcs_f4(K + i2);
        float4 q3 = ldcs_f4(Q + i3);
        float4 k3 = ldcs_f4(K + i3);
        dQ[i]  = pack4_fp8(q0);  dK[i]  = pack4_fp8(k0);
        dQ[i1] = pack4_fp8(q1);  dK[i1] = pack4_fp8(k1);
        dQ[i2] = pack4_fp8(q2);  dK[i2] = pack4_fp8(k2);
        dQ[i3] = pack4_fp8(q3);  dK[i3] = pack4_fp8(k3);
    }
    for (; i < total16; i += stride) {
        float4 q0 = ldcs_f4(Q + i);
        float4 k0 = ldcs_f4(K + i);
        dQ[i] = pack4_fp8(q0);
        dK[i] = pack4_fp8(k0);
    }
    pdl_launch_dependents();
}

__device__ __forceinline__ float dot_fp8_u4(uint4 q, uint4 k) {
    __half2 acc = __floats2half2_rn(0.0f, 0.0f);
    #pragma unroll
    for (int j = 0; j < 4; j++) {
        unsigned qw = (&q.x)[j];
        unsigned kw = (&k.x)[j];
        __half2_raw q0 = __nv_cvt_fp8x2_to_halfraw2((__nv_fp8x2_storage_t)(qw & 0xffffu), __NV_E4M3);
        __half2_raw q1 = __nv_cvt_fp8x2_to_halfraw2((__nv_fp8x2_storage_t)(qw >> 16),     __NV_E4M3);
        __half2_raw k0 = __nv_cvt_fp8x2_to_halfraw2((__nv_fp8x2_storage_t)(kw & 0xffffu), __NV_E4M3);
        __half2_raw k1 = __nv_cvt_fp8x2_to_halfraw2((__nv_fp8x2_storage_t)(kw >> 16),     __NV_E4M3);
        acc = __hfma2(*(__half2*)&q0, *(__half2*)&k0, acc);
        acc = __hfma2(*(__half2*)&q1, *(__half2*)&k1, acc);
    }
    float2 f = __half22float2(acc);
    return f.x + f.y;
}

// CHAMPION CONFIG — at the LTS chip cap; do not perturb.
// 4 lanes per edge, 2 edges per group slot -> 16 edges per warp (MLP=4).
// c/u index loads issued before pdl_wait (independent of convert).
__global__ void edge_kernel(const int* __restrict__ c,
                            const int* __restrict__ u,
                            int num_edges) {
    const unsigned FULL = 0xffffffffu;
    int lane = threadIdx.x & 31;
    int grp  = lane >> 2;        // slot within warp (0..7)
    int li   = lane & 3;         // lane within 4-lane group
    int warp_id = (blockIdx.x * (blockDim.x >> 5)) + (threadIdx.x >> 5);
    int base = warp_id * 16;
    int e0 = base + grp;
    int e1 = base + 8 + grp;

    bool v0 = (e0 < num_edges);
    bool v1 = (e1 < num_edges);

    int c0 = 0, u0 = 0, c1 = 0, u1 = 0;
    if (v0) { c0 = ldcs_i(c + e0); u0 = ldcs_i(u + e0); }
    if (v1) { c1 = ldcs_i(c + e1); u1 = ldcs_i(u + e1); }

    // Wait for convert grid to complete before touching gQ8/gK8/g_node_sum.
    pdl_wait();

    float d0 = 0.0f, d1 = 0.0f;
    if (v0) {
        uint4 q = gQ8[c0 * 4 + li];
        uint4 k = gK8[u0 * 4 + li];
        d0 = dot_fp8_u4(q, k);
    }
    if (v1) {
        uint4 q = gQ8[c1 * 4 + li];
        uint4 k = gK8[u1 * 4 + li];
        d1 = dot_fp8_u4(q, k);
    }

    d0 += __shfl_xor_sync(FULL, d0, 1);
    d0 += __shfl_xor_sync(FULL, d0, 2);
    d1 += __shfl_xor_sync(FULL, d1, 1);
    d1 += __shfl_xor_sync(FULL, d1, 2);

    pdl_launch_dependents();

    if (li == 0) {
        if (v0) atomicAdd(&g_node_sum[c0], __expf(d0 * 0.125f));
        if (v1) atomicAdd(&g_node_sum[c1], __expf(d1 * 0.125f));
    }
}

// Per node: lse = log(sum) (0 for empty). batch is sorted -> warp-segmented
// reduction, only segment heads hit the per-graph atomic.
__global__ void node_kernel(const int* __restrict__ batch,
                            float* __restrict__ out,
                            int num_nodes) {
    const unsigned FULL = 0xffffffffu;
    int n = blockIdx.x * blockDim.x + threadIdx.x;
    int lane = threadIdx.x & 31;

    bool valid = (n < num_nodes);
    int b = -1;
    if (valid) b = ldcs_i(batch + n);

    // Wait for edge grid (g_node_sum complete; transitively, out zeroed).
    pdl_wait();

    float v = 0.0f;
    if (valid) {
        float s = __ldcs(&g_node_sum[n]);
        v = (s > 0.0f) ? __logf(s) : 0.0f;
    }
    #pragma unroll
    for (int off = 1; off < 32; off <<= 1) {
        float ov = __shfl_down_sync(FULL, v, off);
        int   ob = __shfl_down_sync(FULL, b, off);
        if (lane + off < 32 && ob == b) v += ov;
    }
    int bprev = __shfl_up_sync(FULL, b, 1);
    bool head = (lane == 0) || (bprev != b);
    if (valid && head) {
        atomicAdd(&out[b], v);
    }
}

extern "C" void kernel_launch(void* const* d_in, const int* in_sizes, int n_in,
                              void* d_out, int out_size) {
    const float4* Q   = (const float4*)d_in[0];
    const float4* K   = (const float4*)d_in[1];
    const int* c      = (const int*)d_in[2];
    const int* u      = (const int*)d_in[3];
    const int* batch  = (const int*)d_in[4];

    int num_nodes  = in_sizes[0] / 64;
    int num_edges  = in_sizes[2];
    int num_graphs = out_size;
    float* out = (float*)d_out;

    // 1) convert + zero (normal launch, coalesced mapping, 4x unroll)
    {
        int total16 = num_nodes * 16;
        int blocks = 148 * 8;
        convert_zero_kernel<<<blocks, 256>>>(Q, K, out, total16,
                                             num_nodes, num_graphs);
    }
    // 2) edge kernel, PDL-dependent on convert
    {
        int threads = 256;
        int edges_per_block = (threads / 32) * 16;   // 128
        int blocks = (num_edges + edges_per_block - 1) / edges_per_block;

        cudaLaunchConfig_t cfg = {};
        cfg.gridDim = dim3((unsigned)blocks);
        cfg.blockDim = dim3((unsigned)threads);
        cudaLaunchAttribute attr[1];
        attr[0].id = cudaLaunchAttributeProgrammaticStreamSerialization;
        attr[0].val.programmaticStreamSerializationAllowed = 1;
        cfg.attrs = attr;
        cfg.numAttrs = 1;
        cudaLaunchKernelEx(&cfg, edge_kernel, c, u, num_edges);
    }
    // 3) node kernel, PDL-dependent on edge
    {
        int blocks = (num_nodes + 511) / 512;

        cudaLaunchConfig_t cfg = {};
        cfg.gridDim = dim3((unsigned)blocks);
        cfg.blockDim = dim3(512);
        cudaLaunchAttribute attr[1];
        attr[0].id = cudaLaunchAttributeProgrammaticStreamSerialization;
        attr[0].val.programmaticStreamSerializationAllowed = 1;
        cfg.attrs = attr;
        cfg.numAttrs = 1;
        cudaLaunchKernelEx(&cfg, node_kernel, batch, out, num_nodes);
    }
}

// round 15
// speedup vs baseline: 1.0354x; 1.0354x over previous
#include <cuda_runtime.h>
#include <cuda_bf16.h>
#include <cuda_fp8.h>
#include <math.h>

// ----- scratch (no allocations allowed) -----
#define NODE_CAP 131072
__device__ float g_node_sum[NODE_CAP];
// fp8(e4m3) copies of Q,K: one row = 64 fp8 = 64 B = 4 uint4
__device__ uint4 gQ8[NODE_CAP * 4];
__device__ uint4 gK8[NODE_CAP * 4];

// --- PDL primitives (sm_90+) ---
__device__ __forceinline__ void pdl_wait() {
    asm volatile("griddepcontrol.wait;" ::: "memory");
}
__device__ __forceinline__ void pdl_launch_dependents() {
    asm volatile("griddepcontrol.launch_dependents;" ::: "memory");
}

__device__ __forceinline__ unsigned pack4_fp8(float4 a) {
    unsigned short lo = __nv_cvt_float2_to_fp8x2(make_float2(a.x, a.y), __NV_SATFINITE, __NV_E4M3);
    unsigned short hi = __nv_cvt_float2_to_fp8x2(make_float2(a.z, a.w), __NV_SATFINITE, __NV_E4M3);
    return (unsigned)lo | ((unsigned)hi << 16);
}

// fp32 -> fp8 conversion, transposed coalesced mapping (thread i -> one float4),
// manually unrolled 2x (indices i and i+stride): 4 LDG.128 in flight, regs low
// enough for full occupancy (4x unroll regressed via occupancy 88->66%).
// Fused zeroing of g_node_sum and out.
__global__ void convert_zero_kernel(const float4* __restrict__ Q,
                                    const float4* __restrict__ K,
                                    float* __restrict__ out,
                                    int total16 /* num_nodes*16 */,
                                    int num_nodes, int num_graphs) {
    unsigned* dQ = (unsigned*)gQ8;
    unsigned* dK = (unsigned*)gK8;
    int stride = gridDim.x * blockDim.x;
    int i = blockIdx.x * blockDim.x + threadIdx.x;
    if (i < num_nodes) g_node_sum[i] = 0.0f;
    if (i < num_graphs) out[i] = 0.0f;

    for (; i + stride < total16; i += 2 * stride) {
        int j = i + stride;
        float4 q0 = Q[i];
        float4 k0 = K[i];
        float4 q1 = Q[j];
        float4 k1 = K[j];
        dQ[i] = pack4_fp8(q0);
        dK[i] = pack4_fp8(k0);
        dQ[j] = pack4_fp8(q1);
        dK[j] = pack4_fp8(k1);
    }
    if (i < total16) {
        float4 q0 = Q[i];
        float4 k0 = K[i];
        dQ[i] = pack4_fp8(q0);
        dK[i] = pack4_fp8(k0);
    }
    pdl_launch_dependents();
}

__device__ __forceinline__ float dot_fp8_u4(uint4 q, uint4 k) {
    __half2 acc = __floats2half2_rn(0.0f, 0.0f);
    #pragma unroll
    for (int j = 0; j < 4; j++) {
        unsigned qw = (&q.x)[j];
        unsigned kw = (&k.x)[j];
        __half2_raw q0 = __nv_cvt_fp8x2_to_halfraw2((__nv_fp8x2_storage_t)(qw & 0xffffu), __NV_E4M3);
        __half2_raw q1 = __nv_cvt_fp8x2_to_halfraw2((__nv_fp8x2_storage_t)(qw >> 16),     __NV_E4M3);
        __half2_raw k0 = __nv_cvt_fp8x2_to_halfraw2((__nv_fp8x2_storage_t)(kw & 0xffffu), __NV_E4M3);
        __half2_raw k1 = __nv_cvt_fp8x2_to_halfraw2((__nv_fp8x2_storage_t)(kw >> 16),     __NV_E4M3);
        acc = __hfma2(*(__half2*)&q0, *(__half2*)&k0, acc);
        acc = __hfma2(*(__half2*)&q1, *(__half2*)&k1, acc);
    }
    float2 f = __half22float2(acc);
    return f.x + f.y;
}

// CHAMPION CONFIG — at the LTS chip cap; verified optimal from both directions.
// 4 lanes per edge, 2 edges per group slot -> 16 edges per warp (MLP=4).
// c/u index loads issued before pdl_wait (independent of convert).
__global__ void edge_kernel(const int* __restrict__ c,
                            const int* __restrict__ u,
                            int num_edges) {
    const unsigned FULL = 0xffffffffu;
    int lane = threadIdx.x & 31;
    int grp  = lane >> 2;        // slot within warp (0..7)
    int li   = lane & 3;         // lane within 4-lane group
    int warp_id = (blockIdx.x * (blockDim.x >> 5)) + (threadIdx.x >> 5);
    int base = warp_id * 16;
    int e0 = base + grp;
    int e1 = base + 8 + grp;

    bool v0 = (e0 < num_edges);
    bool v1 = (e1 < num_edges);

    int c0 = 0, u0 = 0, c1 = 0, u1 = 0;
    if (v0) { c0 = c[e0]; u0 = u[e0]; }
    if (v1) { c1 = c[e1]; u1 = u[e1]; }

    // Wait for convert grid to complete before touching gQ8/gK8/g_node_sum.
    pdl_wait();

    float d0 = 0.0f, d1 = 0.0f;
    if (v0) {
        uint4 q = gQ8[c0 * 4 + li];
        uint4 k = gK8[u0 * 4 + li];
        d0 = dot_fp8_u4(q, k);
    }
    if (v1) {
        uint4 q = gQ8[c1 * 4 + li];
        uint4 k = gK8[u1 * 4 + li];
        d1 = dot_fp8_u4(q, k);
    }

    d0 += __shfl_xor_sync(FULL, d0, 1);
    d0 += __shfl_xor_sync(FULL, d0, 2);
    d1 += __shfl_xor_sync(FULL, d1, 1);
    d1 += __shfl_xor_sync(FULL, d1, 2);

    pdl_launch_dependents();

    if (li == 0) {
        if (v0) atomicAdd(&g_node_sum[c0], __expf(d0 * 0.125f));
        if (v1) atomicAdd(&g_node_sum[c1], __expf(d1 * 0.125f));
    }
}

// Per node: lse = log(sum) (0 for empty). batch is sorted -> warp-segmented
// reduction, only segment heads hit the per-graph atomic.
// PDL: batch load is independent of edge output -> load before the wait.
__global__ void node_kernel(const int* __restrict__ batch,
                            float* __restrict__ out,
                            int num_nodes) {
    const unsigned FULL = 0xffffffffu;
    int n = blockIdx.x * blockDim.x + threadIdx.x;
    int lane = threadIdx.x & 31;

    bool valid = (n < num_nodes);
    int b = -1;
    if (valid) b = batch[n];

    // Wait for edge grid (g_node_sum complete; transitively, out zeroed).
    pdl_wait();

    float v = 0.0f;
    if (valid) {
        float s = g_node_sum[n];
        v = (s > 0.0f) ? __logf(s) : 0.0f;
    }
    #pragma unroll
    for (int off = 1; off < 32; off <<= 1) {
        float ov = __shfl_down_sync(FULL, v, off);
        int   ob = __shfl_down_sync(FULL, b, off);
        if (lane + off < 32 && ob == b) v += ov;
    }
    int bprev = __shfl_up_sync(FULL, b, 1);
    bool head = (lane == 0) || (bprev != b);
    if (valid && head) {
        atomicAdd(&out[b], v);
    }
}

extern "C" void kernel_launch(void* const* d_in, const int* in_sizes, int n_in,
                              void* d_out, int out_size) {
    const float4* Q   = (const float4*)d_in[0];
    const float4* K   = (const float4*)d_in[1];
    const int* c      = (const int*)d_in[2];
    const int* u      = (const int*)d_in[3];
    const int* batch  = (const int*)d_in[4];

    int num_nodes  = in_sizes[0] / 64;
    int num_edges  = in_sizes[2];
    int num_graphs = out_size;
    float* out = (float*)d_out;

    // 1) convert + zero (normal launch, transposed coalesced mapping, 2x unroll)
    {
        int total16 = num_nodes * 16;
        int blocks = 148 * 8;
        convert_zero_kernel<<<blocks, 256>>>(Q, K, out, total16,
                                             num_nodes, num_graphs);
    }
    // 2) edge kernel, PDL-dependent on convert
    {
        int threads = 256;
        int edges_per_block = (threads / 32) * 16;   // 128
        int blocks = (num_edges + edges_per_block - 1) / edges_per_block;

        cudaLaunchConfig_t cfg = {};
        cfg.gridDim = dim3((unsigned)blocks);
        cfg.blockDim = dim3((unsigned)threads);
        cudaLaunchAttribute attr[1];
        attr[0].id = cudaLaunchAttributeProgrammaticStreamSerialization;
        attr[0].val.programmaticStreamSerializationAllowed = 1;
        cfg.attrs = attr;
        cfg.numAttrs = 1;
        cudaLaunchKernelEx(&cfg, edge_kernel, c, u, num_edges);
    }
    // 3) node kernel, PDL-dependent on edge
    {
        int blocks = (num_nodes + 511) / 512;

        cudaLaunchConfig_t cfg = {};
        cfg.gridDim = dim3((unsigned)blocks);
        cfg.blockDim = dim3(512);
        cudaLaunchAttribute attr[1];
        attr[0].id = cudaLaunchAttributeProgrammaticStreamSerialization;
        attr[0].val.programmaticStreamSerializationAllowed = 1;
        cfg.attrs = attr;
        cfg.numAttrs = 1;
        cudaLaunchKernelEx(&cfg, node_kernel, batch, out, num_nodes);
    }
}